// round 13
// baseline (speedup 1.0000x reference)
#include <cuda_runtime.h>
#include <cstdint>

#define FULL_MASK 0xffffffffu

// B=4, T=32, N=4096, F=16, G=64, M=128, K=32, C0=64, C1=128
#define NPTS   4096
#define NGRP   64
#define NANCH  128
#define XYZ_OUT_ELEMS (64 * 128 * 3)   // 24576
#define R2CONST 0.0225f

typedef unsigned long long u64t;

static __device__ __forceinline__ u64t pack2(float lo, float hi) {
    u64t r;
    asm("mov.b64 %0, {%1, %2};" : "=l"(r) : "f"(lo), "f"(hi));
    return r;
}
static __device__ __forceinline__ void fma2(u64t &acc, u64t a, u64t b) {
    asm("fma.rn.f32x2 %0, %1, %2, %0;" : "+l"(acc) : "l"(a), "l"(b));
}
static __device__ __forceinline__ void add2(u64t &a, u64t b) {
    asm("add.rn.f32x2 %0, %0, %1;" : "+l"(a) : "l"(b));
}
static __device__ __forceinline__ float sum2(u64t v) {
    float a, b;
    asm("mov.b64 {%0, %1}, %2;" : "=f"(a), "=f"(b) : "l"(v));
    return a + b;
}
// Warp max of NON-NEGATIVE floats via integer redux (bits monotone for >=0).
static __device__ __forceinline__ unsigned warp_max_bits(unsigned s) {
    unsigned r;
    asm volatile("redux.sync.max.u32 %0, %1, 0xffffffff;" : "=r"(r) : "r"(s));
    return r;
}
static __device__ __forceinline__ float warp_max_nn(float s) {
    return __uint_as_float(warp_max_bits(__float_as_uint(s)));
}

// ---------------------------------------------------------------------------
// Kernel 1: furthest point sampling. One block per group (64 blocks).
// Argmax via redux.sync.max.u32 on distance bits; tie -> lowest lane =
// earliest point index (blocked ownership preserves reference semantics).
// ---------------------------------------------------------------------------
__global__ __launch_bounds__(512) void fps_kernel(const float* __restrict__ xyzs,
                                                  float* __restrict__ out)
{
    __shared__ float sx[NPTS], sy[NPTS], sz[NPTS];
    __shared__ unsigned wvb[16];
    __shared__ int      wib[16];
    __shared__ float bc[3];

    const int g = blockIdx.x;
    const int b = g >> 4;
    const int f = g & 15;
    const int tc = 2 * f;
    const float* fr = xyzs + (size_t)((b * 32 + tc) * NPTS) * 3;

    const int tid  = threadIdx.x;
    const int lane = tid & 31;
    const int warp = tid >> 5;

    float px[8], py[8], pz[8], dist[8];
#pragma unroll
    for (int j = 0; j < 8; j++) {
        int p = tid * 8 + j;
        float x = fr[p * 3 + 0];
        float y = fr[p * 3 + 1];
        float z = fr[p * 3 + 2];
        px[j] = x; py[j] = y; pz[j] = z;
        sx[p] = x; sy[p] = y; sz[p] = z;
        dist[j] = 1e10f;
    }
    float* anc = out + (size_t)g * NANCH * 3;
    __syncthreads();
    if (tid == 0) {
        bc[0] = sx[0]; bc[1] = sy[0]; bc[2] = sz[0];
        anc[0] = sx[0]; anc[1] = sy[0]; anc[2] = sz[0];
    }
    __syncthreads();

    for (int it = 1; it < NANCH; it++) {
        const float cx = bc[0], cy = bc[1], cz = bc[2];
        float bd = -1.0f;
        int   bi = 0;
#pragma unroll
        for (int j = 0; j < 8; j++) {
            float dx = px[j] - cx, dy = py[j] - cy, dz = pz[j] - cz;
            float d = dx * dx + dy * dy + dz * dz;
            d = fminf(dist[j], d);
            dist[j] = d;
            if (d > bd) { bd = d; bi = tid * 8 + j; }   // strict > keeps earliest index
        }
        // warp argmax: redux on bits, tie -> lowest lane (earliest chunk)
        const unsigned mb = __float_as_uint(bd);        // bd >= 0
        const unsigned mx = warp_max_bits(mb);
        const unsigned eq = __ballot_sync(FULL_MASK, mb == mx);
        const int      wl = __ffs(eq) - 1;
        const int     wbi = __shfl_sync(FULL_MASK, bi, wl);
        if (lane == 0) { wvb[warp] = mx; wib[warp] = wbi; }
        __syncthreads();
        if (warp == 0) {
            const unsigned vb = (lane < 16) ? wvb[lane] : 0u;
            const unsigned m2 = warp_max_bits(vb);
            const unsigned e2 = __ballot_sync(FULL_MASK, (vb == m2) && (lane < 16));
            const int      l2 = __ffs(e2) - 1;
            if (lane == l2) {
                const int i2 = wib[l2];
                float nx = sx[i2], ny = sy[i2], nz = sz[i2];
                bc[0] = nx; bc[1] = ny; bc[2] = nz;
                anc[it * 3 + 0] = nx;
                anc[it * 3 + 1] = ny;
                anc[it * 3 + 2] = nz;
            }
        }
        __syncthreads();
    }
}

// ---------------------------------------------------------------------------
// Kernel 2: ball query + MLP(4->64) + MLP(64->128) + max over neighbors.
// One warp per anchor, lane = neighbor. Ball query vectorized: lane owns 4
// consecutive points per 128-pt batch via 3x LDG.128. h1 resident in 32 f32x2
// regs; Wm rows broadcast LDS.128; warp max via redux.sync.max.u32.
// ---------------------------------------------------------------------------
__global__ __launch_bounds__(128, 4) void p4d_kernel(const float* __restrict__ xyzs,
                                                     const float* __restrict__ Wd,
                                                     const float* __restrict__ Wm,
                                                     float* __restrict__ out)
{
    __shared__ __align__(16) float Wm_s[128 * 64];
    __shared__ __align__(16) float Wd_s[256];
    __shared__ int sel[4][32];

    const int tid = threadIdx.x;
    {
        const float4* gWm = (const float4*)Wm;
        float4*       sWm = (float4*)Wm_s;
        for (int i = tid; i < 128 * 16; i += 128) sWm[i] = gWm[i];
        Wd_s[tid]       = Wd[tid];
        Wd_s[tid + 128] = Wd[tid + 128];
    }
    __syncthreads();

    const int lane = tid & 31;
    const int w    = tid >> 5;
    const int a    = blockIdx.x * 4 + w;      // global anchor id 0..8191
    const int g    = a >> 7;
    const int m    = a & 127;
    const int b    = g >> 4;
    const int f    = g & 15;
    const int tc   = 2 * f;

    const float* anc = out + (size_t)(g * NANCH + m) * 3;
    const float ax = anc[0], ay = anc[1], az = anc[2];

    const float4* Wd4  = (const float4*)Wd_s;
    int*          selw = sel[w];

    float facc0 = 0.f, facc1 = 0.f, facc2 = 0.f, facc3 = 0.f;

    for (int dti = 0; dti < 3; dti++) {
        const int t = (dti == 0) ? ((f == 0) ? 0 : (tc - 1))
                                 : ((dti == 1) ? tc : (tc + 1));
        const float* fr  = xyzs + (size_t)((b * 32 + t) * NPTS) * 3;
        const float  dtf = (float)(dti - 1);

        // ---- ball query: first 32 in-radius (ascending idx), pad with first.
        //      Lane owns points 4*lane..4*lane+3 of each 128-pt batch, loaded
        //      as 3 float4 (16B-aligned: frame base and batch stride are).
        __syncwarp();
        int cnt = 0;
        for (int base = 0; base < NPTS && cnt < 32; base += 128) {
            const float4* fp = (const float4*)(fr + (size_t)base * 3);
            const float4 A = fp[3 * lane + 0];
            const float4 Bv = fp[3 * lane + 1];
            const float4 C = fp[3 * lane + 2];
            float q0x = A.x - ax,  q0y = A.y - ay,  q0z = A.z - az;
            float q1x = A.w - ax,  q1y = Bv.x - ay, q1z = Bv.y - az;
            float q2x = Bv.z - ax, q2y = Bv.w - ay, q2z = C.x - az;
            float q3x = C.y - ax,  q3y = C.z - ay,  q3z = C.w - az;
            const bool p0 = (q0x * q0x + q0y * q0y + q0z * q0z) < R2CONST;
            const bool p1 = (q1x * q1x + q1y * q1y + q1z * q1z) < R2CONST;
            const bool p2 = (q2x * q2x + q2y * q2y + q2z * q2z) < R2CONST;
            const bool p3 = (q3x * q3x + q3y * q3y + q3z * q3z) < R2CONST;
            const unsigned m0 = __ballot_sync(FULL_MASK, p0);
            const unsigned m1 = __ballot_sync(FULL_MASK, p1);
            const unsigned m2 = __ballot_sync(FULL_MASK, p2);
            const unsigned m3 = __ballot_sync(FULL_MASK, p3);
            const unsigned below = (1u << lane) - 1u;
            int r = cnt + __popc(m0 & below) + __popc(m1 & below)
                        + __popc(m2 & below) + __popc(m3 & below);
            const int pbase = base + 4 * lane;
            if (p0) { if (r < 32) selw[r] = pbase + 0; r++; }
            if (p1) { if (r < 32) selw[r] = pbase + 1; r++; }
            if (p2) { if (r < 32) selw[r] = pbase + 2; r++; }
            if (p3) { if (r < 32) selw[r] = pbase + 3; r++; }
            cnt += __popc(m0) + __popc(m1) + __popc(m2) + __popc(m3);
        }
        __syncwarp();
        const int pad = (cnt > 0) ? selw[0] : 0;
        const int myN = (lane < cnt) ? selw[lane] : pad;

        const float nx = fr[myN * 3 + 0];
        const float ny = fr[myN * 3 + 1];
        const float nz = fr[myN * 3 + 2];
        const float dx = nx - ax, dy = ny - ay, dz = nz - az;

        // ---- h1 = relu(Wd @ [dx,dy,dz,dt]) : 64 values in regs as 32 f32x2
        u64t Hp[32];
#pragma unroll
        for (int i2 = 0; i2 < 32; i2++) {
            const float4 w0 = Wd4[2 * i2];
            const float4 w1 = Wd4[2 * i2 + 1];
            float a0 = fmaxf(w0.x * dx + w0.y * dy + w0.z * dz + w0.w * dtf, 0.f);
            float a1 = fmaxf(w1.x * dx + w1.y * dy + w1.z * dz + w1.w * dtf, 0.f);
            Hp[i2] = pack2(a0, a1);
        }

        // ---- h2 = Wm @ h1 per lane(=neighbor); relu then warp max per channel.
#pragma unroll
        for (int cc = 0; cc < 4; cc++) {
            float fa = 0.f;
#pragma unroll 2
            for (int ol = 0; ol < 32; ol++) {
                const ulonglong2* wr =
                    (const ulonglong2*)(Wm_s + ((cc * 32 + ol) << 6));
                u64t a0 = 0ull, a1 = 0ull, a2 = 0ull, a3 = 0ull;
#pragma unroll
                for (int k = 0; k < 8; k++) {
                    ulonglong2 p = wr[2 * k];
                    ulonglong2 q = wr[2 * k + 1];
                    fma2(a0, p.x, Hp[4 * k + 0]);
                    fma2(a1, p.y, Hp[4 * k + 1]);
                    fma2(a2, q.x, Hp[4 * k + 2]);
                    fma2(a3, q.y, Hp[4 * k + 3]);
                }
                add2(a0, a1);
                add2(a2, a3);
                add2(a0, a2);
                const float r = warp_max_nn(fmaxf(sum2(a0), 0.f));
                if (ol == lane) fa += r;
            }
            if      (cc == 0) facc0 += fa;
            else if (cc == 1) facc1 += fa;
            else if (cc == 2) facc2 += fa;
            else              facc3 += fa;
        }
    }

    // new_features[b][f][c][m] at 24576 + (g*128 + c)*128 + m
    float* fo = out + XYZ_OUT_ELEMS + (size_t)(g * 128) * 128 + m;
    fo[(size_t)(lane +  0) * 128] = facc0;
    fo[(size_t)(lane + 32) * 128] = facc1;
    fo[(size_t)(lane + 64) * 128] = facc2;
    fo[(size_t)(lane + 96) * 128] = facc3;
}

// ---------------------------------------------------------------------------
extern "C" void kernel_launch(void* const* d_in, const int* in_sizes, int n_in,
                              void* d_out, int out_size)
{
    const float* xyzs = (const float*)d_in[0];   // (4,32,4096,3) f32
    const float* Wd   = (const float*)d_in[1];   // (64,4) f32
    const float* Wm   = (const float*)d_in[2];   // (128,64) f32
    float* out = (float*)d_out;                  // 24576 xyz + 262144 feat

    fps_kernel<<<NGRP, 512>>>(xyzs, out);
    p4d_kernel<<<2048, 128>>>(xyzs, Wd, Wm, out);
}